// round 4
// baseline (speedup 1.0000x reference)
#include <cuda_runtime.h>
#include <math.h>

// ForestRuthIntegrator — fp32 SIMT v2.1.
// v2 + the missing __syncthreads() before the tid-linear output epilogue
// (final xup writes sx warp-private; epilogue reads it tid-linear -> must barrier).

#define THREADS 512
#define CTA_M   32
#define DDIM    512
#define KDIM    64
#define H2S     34          // sh2t row stride (pad, keeps 8B align)

__device__ __forceinline__ float wrap_torus(float x) {
    const float PI_F     = 3.14159274101257324f;   // float32(pi)
    const float TWO_PI_F = 6.28318548202514648f;   // exactly 2*PI_F
    float t = __fadd_rn(x, PI_F);
    // t in (-2pi, 4pi): single conditional sub/add is bitwise == fmodf path
    if (t >= TWO_PI_F) t = __fsub_rn(t, TWO_PI_F);  // exact (Sterbenz, t<=4pi)
    if (t < 0.0f)      t = __fadd_rn(t, TWO_PI_F);  // mod sign fixup
    return __fsub_rn(t, PI_F);
}

__device__ __forceinline__ void cp16(float* dst_smem, const float* src) {
    unsigned s = (unsigned)__cvta_generic_to_shared(dst_smem);
    asm volatile("cp.async.cg.shared.global [%0], [%1], 16;" :: "r"(s), "l"(src));
}
#define CP_COMMIT() asm volatile("cp.async.commit_group;")
#define CP_WAIT1()  asm volatile("cp.async.wait_group 1;")
#define CP_WAIT0()  asm volatile("cp.async.wait_group 0;")

__global__ __launch_bounds__(THREADS, 1)
void fr_kernel(const float* __restrict__ gx, const float* __restrict__ gv,
               const float* __restrict__ gf, const float* __restrict__ gU,
               const float* __restrict__ gW, const int* __restrict__ gsteps,
               float* __restrict__ gox, float* __restrict__ gov,
               float c1dt, float c2dt, float d1dt, float d2dt)
{
    extern __shared__ float smem[];
    float* sx    = smem;                    // [32][512] 64KB
    float* sv    = sx + CTA_M * DDIM;       // [32][512] 64KB
    float* sh2t  = sv + CTA_M * DDIM;       // [64][H2S] transposed h^2
    float* stage = sh2t + KDIM * H2S;       // 2 x 8192 floats ping-pong, 64KB

    const int tid  = threadIdx.x;
    const int w    = tid >> 5;              // warp 0..15 -> rows 2w, 2w+1
    const int lane = tid & 31;
    const int row0 = blockIdx.x * CTA_M;
    const int r0 = 2 * w, r1 = 2 * w + 1;

    // chunk ids: 0..3 = U rows [128c..128c+128), 4..7 = W cols [128(c-4)..)
    auto issue_chunk = [&](int cid) {
        float* dst = stage + (cid & 1) * 8192;
        if (cid < 4) {
            const float* src = gU + (size_t)cid * 8192;
            #pragma unroll
            for (int i = 0; i < 4; ++i) {
                int idx = tid + i * THREADS;
                cp16(dst + idx * 4, src + idx * 4);
            }
        } else {
            const float* src = gW + (cid - 4) * 128;
            #pragma unroll
            for (int i = 0; i < 4; ++i) {
                int idx = tid + i * THREADS;
                int k = idx >> 5, seg = idx & 31;
                cp16(dst + k * 128 + seg * 4, src + (size_t)k * DDIM + seg * 4);
            }
        }
        CP_COMMIT();
    };

    issue_chunk(0);
    issue_chunk(1);
    {
        const float4* gx4 = (const float4*)(gx + (size_t)row0 * DDIM);
        const float4* gv4 = (const float4*)(gv + (size_t)row0 * DDIM);
        float4* sx4 = (float4*)sx;
        float4* sv4 = (float4*)sv;
        #pragma unroll
        for (int i = 0; i < 8; ++i) {
            sx4[tid + i * THREADS] = gx4[tid + i * THREADS];
            sv4[tid + i * THREADS] = gv4[tid + i * THREADS];
        }
    }
    __syncthreads();

    const int steps = gsteps ? gsteps[0] : 4;

    auto xup = [&](float cdt) {
        #pragma unroll
        for (int i = 0; i < 2; ++i) {
            const int r = 2 * w + i;
            #pragma unroll
            for (int ch = 0; ch < 4; ++ch) {
                const int c = ch * 128 + lane * 4;
                float4 xv = *(float4*)(sx + r * DDIM + c);
                float4 vv = *(const float4*)(sv + r * DDIM + c);
                xv.x = wrap_torus(__fadd_rn(xv.x, __fmul_rn(cdt, vv.x)));
                xv.y = wrap_torus(__fadd_rn(xv.y, __fmul_rn(cdt, vv.y)));
                xv.z = wrap_torus(__fadd_rn(xv.z, __fmul_rn(cdt, vv.z)));
                xv.w = wrap_torus(__fadd_rn(xv.w, __fmul_rn(cdt, vv.w)));
                *(float4*)(sx + r * DDIM + c) = xv;
            }
        }
    };

    auto eval = [&](float ddt) {
        // GEMM1: h[2 rows][2 k] over d, chunked & double-buffered
        float a00 = 0.f, a01 = 0.f, a10 = 0.f, a11 = 0.f;
        const float* svr0 = sv + r0 * DDIM;
        const float* svr1 = sv + r1 * DDIM;
        #pragma unroll 1
        for (int c = 0; c < 4; ++c) {
            CP_WAIT1();
            __syncthreads();
            const float* sU = stage + (c & 1) * 8192;
            const float* p0 = svr0 + c * 128;
            const float* p1 = svr1 + c * 128;
            const float* ub = sU + 2 * lane;
            #pragma unroll 8
            for (int d4 = 0; d4 < 32; ++d4) {
                float4 v0 = *(const float4*)(p0 + d4 * 4);
                float4 v1 = *(const float4*)(p1 + d4 * 4);
                const float* u = ub + (d4 * 4) * KDIM;
                float2 t;
                t = *(const float2*)(u);
                a00 = fmaf(v0.x, t.x, a00); a01 = fmaf(v0.x, t.y, a01);
                a10 = fmaf(v1.x, t.x, a10); a11 = fmaf(v1.x, t.y, a11);
                t = *(const float2*)(u + KDIM);
                a00 = fmaf(v0.y, t.x, a00); a01 = fmaf(v0.y, t.y, a01);
                a10 = fmaf(v1.y, t.x, a10); a11 = fmaf(v1.y, t.y, a11);
                t = *(const float2*)(u + 2 * KDIM);
                a00 = fmaf(v0.z, t.x, a00); a01 = fmaf(v0.z, t.y, a01);
                a10 = fmaf(v1.z, t.x, a10); a11 = fmaf(v1.z, t.y, a11);
                t = *(const float2*)(u + 3 * KDIM);
                a00 = fmaf(v0.w, t.x, a00); a01 = fmaf(v0.w, t.y, a01);
                a10 = fmaf(v1.w, t.x, a10); a11 = fmaf(v1.w, t.y, a11);
            }
            __syncthreads();
            issue_chunk(c + 2);   // 2,3 -> U; then 4,5 -> W0,W1
        }
        // h^2, transposed [k][row] — warp-local columns r0,r1
        sh2t[(2 * lane)     * H2S + r0] = __fmul_rn(a00, a00);
        sh2t[(2 * lane + 1) * H2S + r0] = __fmul_rn(a01, a01);
        sh2t[(2 * lane)     * H2S + r1] = __fmul_rn(a10, a10);
        sh2t[(2 * lane + 1) * H2S + r1] = __fmul_rn(a11, a11);
        __syncwarp();

        // GEMM2: christ[2 rows][4 cols] over k; fused v-update
        #pragma unroll 1
        for (int c = 0; c < 4; ++c) {
            CP_WAIT1();
            __syncthreads();
            const float* sW = stage + (c & 1) * 8192;
            const int col = c * 128 + lane * 4;
            const float4 f0 = *(const float4*)(gf + (size_t)(row0 + r0) * DDIM + col);
            const float4 f1 = *(const float4*)(gf + (size_t)(row0 + r1) * DDIM + col);
            float b00 = 0.f, b01 = 0.f, b02 = 0.f, b03 = 0.f;
            float b10 = 0.f, b11 = 0.f, b12 = 0.f, b13 = 0.f;
            const float* wb = sW + lane * 4;
            const float* hb = sh2t + r0;
            #pragma unroll 8
            for (int k = 0; k < KDIM; ++k) {
                float4 wv = *(const float4*)(wb + k * 128);
                float2 hh = *(const float2*)(hb + k * H2S);
                b00 = fmaf(hh.x, wv.x, b00); b01 = fmaf(hh.x, wv.y, b01);
                b02 = fmaf(hh.x, wv.z, b02); b03 = fmaf(hh.x, wv.w, b03);
                b10 = fmaf(hh.y, wv.x, b10); b11 = fmaf(hh.y, wv.y, b11);
                b12 = fmaf(hh.y, wv.z, b12); b13 = fmaf(hh.y, wv.w, b13);
            }
            float4 vv0 = *(float4*)(sv + r0 * DDIM + col);
            vv0.x = __fadd_rn(vv0.x, __fmul_rn(ddt, __fadd_rn(-b00, f0.x)));
            vv0.y = __fadd_rn(vv0.y, __fmul_rn(ddt, __fadd_rn(-b01, f0.y)));
            vv0.z = __fadd_rn(vv0.z, __fmul_rn(ddt, __fadd_rn(-b02, f0.z)));
            vv0.w = __fadd_rn(vv0.w, __fmul_rn(ddt, __fadd_rn(-b03, f0.w)));
            *(float4*)(sv + r0 * DDIM + col) = vv0;
            float4 vv1 = *(float4*)(sv + r1 * DDIM + col);
            vv1.x = __fadd_rn(vv1.x, __fmul_rn(ddt, __fadd_rn(-b10, f1.x)));
            vv1.y = __fadd_rn(vv1.y, __fmul_rn(ddt, __fadd_rn(-b11, f1.y)));
            vv1.z = __fadd_rn(vv1.z, __fmul_rn(ddt, __fadd_rn(-b12, f1.z)));
            vv1.w = __fadd_rn(vv1.w, __fmul_rn(ddt, __fadd_rn(-b13, f1.w)));
            *(float4*)(sv + r1 * DDIM + col) = vv1;
            __syncthreads();
            issue_chunk((c + 6) & 7);   // 6,7 -> W2,W3; then 0,1 -> next eval's U
        }
    };

    for (int s = 0; s < steps; ++s) {
        xup(c1dt);
        eval(d1dt);
        xup(c2dt);
        eval(d2dt);
        xup(c2dt);   // C3 == C2
        eval(d1dt);  // D3 == D1
        xup(c1dt);   // C4 == C1
    }

    // Epilogue is tid-linear across the whole tile -> MUST barrier after the
    // warp-private final xup. (This was the round-2 bug.)
    __syncthreads();
    {
        float4* gox4 = (float4*)(gox + (size_t)row0 * DDIM);
        float4* gov4 = (float4*)(gov + (size_t)row0 * DDIM);
        const float4* sx4 = (const float4*)sx;
        const float4* sv4 = (const float4*)sv;
        #pragma unroll
        for (int i = 0; i < 8; ++i) {
            gox4[tid + i * THREADS] = sx4[tid + i * THREADS];
            gov4[tid + i * THREADS] = sv4[tid + i * THREADS];
        }
    }
    CP_WAIT0();   // drain dangling prefetch groups before exit
}

extern "C" void kernel_launch(void* const* d_in, const int* in_sizes, int n_in,
                              void* d_out, int out_size)
{
    const float* x = (const float*)d_in[0];
    const float* v = (const float*)d_in[1];
    const float* f = (const float*)d_in[2];
    const float* U = (const float*)d_in[3];
    const float* W = (const float*)d_in[4];
    const int* steps = (n_in >= 6) ? (const int*)d_in[5] : nullptr;

    const int B  = in_sizes[0] / DDIM;
    const int BD = B * DDIM;
    float* ox = (float*)d_out;
    float* ov = ox + BD;

    const double theta = 1.0 / (2.0 - pow(2.0, 1.0 / 3.0));
    const float c1dt = (float)((theta / 2.0) * 0.01);
    const float c2dt = (float)(((1.0 - theta) / 2.0) * 0.01);
    const float d1dt = (float)(theta * 0.01);
    const float d2dt = (float)((1.0 - 2.0 * theta) * 0.01);

    const int smem_bytes = (2 * CTA_M * DDIM + KDIM * H2S + 2 * 8192) * 4;  // 205,312 B
    cudaFuncSetAttribute(fr_kernel, cudaFuncAttributeMaxDynamicSharedMemorySize, smem_bytes);
    fr_kernel<<<B / CTA_M, THREADS, smem_bytes>>>(x, v, f, U, W, steps, ox, ov,
                                                  c1dt, c2dt, d1dt, d2dt);
}

// round 5
// speedup vs baseline: 1.0569x; 1.0569x over previous
#include <cuda_runtime.h>
#include <math.h>

// ForestRuthIntegrator — fp32 SIMT v2.1.
// v2 + the missing __syncthreads() before the tid-linear output epilogue
// (final xup writes sx warp-private; epilogue reads it tid-linear -> must barrier).

#define THREADS 512
#define CTA_M   32
#define DDIM    512
#define KDIM    64
#define H2S     34          // sh2t row stride (pad, keeps 8B align)

__device__ __forceinline__ float wrap_torus(float x) {
    const float PI_F     = 3.14159274101257324f;   // float32(pi)
    const float TWO_PI_F = 6.28318548202514648f;   // exactly 2*PI_F
    float t = __fadd_rn(x, PI_F);
    // t in (-2pi, 4pi): single conditional sub/add is bitwise == fmodf path
    if (t >= TWO_PI_F) t = __fsub_rn(t, TWO_PI_F);  // exact (Sterbenz, t<=4pi)
    if (t < 0.0f)      t = __fadd_rn(t, TWO_PI_F);  // mod sign fixup
    return __fsub_rn(t, PI_F);
}

__device__ __forceinline__ void cp16(float* dst_smem, const float* src) {
    unsigned s = (unsigned)__cvta_generic_to_shared(dst_smem);
    asm volatile("cp.async.cg.shared.global [%0], [%1], 16;" :: "r"(s), "l"(src));
}
#define CP_COMMIT() asm volatile("cp.async.commit_group;")
#define CP_WAIT1()  asm volatile("cp.async.wait_group 1;")
#define CP_WAIT0()  asm volatile("cp.async.wait_group 0;")

__global__ __launch_bounds__(THREADS, 1)
void fr_kernel(const float* __restrict__ gx, const float* __restrict__ gv,
               const float* __restrict__ gf, const float* __restrict__ gU,
               const float* __restrict__ gW, const int* __restrict__ gsteps,
               float* __restrict__ gox, float* __restrict__ gov,
               float c1dt, float c2dt, float d1dt, float d2dt)
{
    extern __shared__ float smem[];
    float* sx    = smem;                    // [32][512] 64KB
    float* sv    = sx + CTA_M * DDIM;       // [32][512] 64KB
    float* sh2t  = sv + CTA_M * DDIM;       // [64][H2S] transposed h^2
    float* stage = sh2t + KDIM * H2S;       // 2 x 8192 floats ping-pong, 64KB

    const int tid  = threadIdx.x;
    const int w    = tid >> 5;              // warp 0..15 -> rows 2w, 2w+1
    const int lane = tid & 31;
    const int row0 = blockIdx.x * CTA_M;
    const int r0 = 2 * w, r1 = 2 * w + 1;

    // chunk ids: 0..3 = U rows [128c..128c+128), 4..7 = W cols [128(c-4)..)
    auto issue_chunk = [&](int cid) {
        float* dst = stage + (cid & 1) * 8192;
        if (cid < 4) {
            const float* src = gU + (size_t)cid * 8192;
            #pragma unroll
            for (int i = 0; i < 4; ++i) {
                int idx = tid + i * THREADS;
                cp16(dst + idx * 4, src + idx * 4);
            }
        } else {
            const float* src = gW + (cid - 4) * 128;
            #pragma unroll
            for (int i = 0; i < 4; ++i) {
                int idx = tid + i * THREADS;
                int k = idx >> 5, seg = idx & 31;
                cp16(dst + k * 128 + seg * 4, src + (size_t)k * DDIM + seg * 4);
            }
        }
        CP_COMMIT();
    };

    issue_chunk(0);
    issue_chunk(1);
    {
        const float4* gx4 = (const float4*)(gx + (size_t)row0 * DDIM);
        const float4* gv4 = (const float4*)(gv + (size_t)row0 * DDIM);
        float4* sx4 = (float4*)sx;
        float4* sv4 = (float4*)sv;
        #pragma unroll
        for (int i = 0; i < 8; ++i) {
            sx4[tid + i * THREADS] = gx4[tid + i * THREADS];
            sv4[tid + i * THREADS] = gv4[tid + i * THREADS];
        }
    }
    __syncthreads();

    const int steps = gsteps ? gsteps[0] : 4;

    auto xup = [&](float cdt) {
        #pragma unroll
        for (int i = 0; i < 2; ++i) {
            const int r = 2 * w + i;
            #pragma unroll
            for (int ch = 0; ch < 4; ++ch) {
                const int c = ch * 128 + lane * 4;
                float4 xv = *(float4*)(sx + r * DDIM + c);
                float4 vv = *(const float4*)(sv + r * DDIM + c);
                xv.x = wrap_torus(__fadd_rn(xv.x, __fmul_rn(cdt, vv.x)));
                xv.y = wrap_torus(__fadd_rn(xv.y, __fmul_rn(cdt, vv.y)));
                xv.z = wrap_torus(__fadd_rn(xv.z, __fmul_rn(cdt, vv.z)));
                xv.w = wrap_torus(__fadd_rn(xv.w, __fmul_rn(cdt, vv.w)));
                *(float4*)(sx + r * DDIM + c) = xv;
            }
        }
    };

    auto eval = [&](float ddt) {
        // GEMM1: h[2 rows][2 k] over d, chunked & double-buffered
        float a00 = 0.f, a01 = 0.f, a10 = 0.f, a11 = 0.f;
        const float* svr0 = sv + r0 * DDIM;
        const float* svr1 = sv + r1 * DDIM;
        #pragma unroll 1
        for (int c = 0; c < 4; ++c) {
            CP_WAIT1();
            __syncthreads();
            const float* sU = stage + (c & 1) * 8192;
            const float* p0 = svr0 + c * 128;
            const float* p1 = svr1 + c * 128;
            const float* ub = sU + 2 * lane;
            #pragma unroll 8
            for (int d4 = 0; d4 < 32; ++d4) {
                float4 v0 = *(const float4*)(p0 + d4 * 4);
                float4 v1 = *(const float4*)(p1 + d4 * 4);
                const float* u = ub + (d4 * 4) * KDIM;
                float2 t;
                t = *(const float2*)(u);
                a00 = fmaf(v0.x, t.x, a00); a01 = fmaf(v0.x, t.y, a01);
                a10 = fmaf(v1.x, t.x, a10); a11 = fmaf(v1.x, t.y, a11);
                t = *(const float2*)(u + KDIM);
                a00 = fmaf(v0.y, t.x, a00); a01 = fmaf(v0.y, t.y, a01);
                a10 = fmaf(v1.y, t.x, a10); a11 = fmaf(v1.y, t.y, a11);
                t = *(const float2*)(u + 2 * KDIM);
                a00 = fmaf(v0.z, t.x, a00); a01 = fmaf(v0.z, t.y, a01);
                a10 = fmaf(v1.z, t.x, a10); a11 = fmaf(v1.z, t.y, a11);
                t = *(const float2*)(u + 3 * KDIM);
                a00 = fmaf(v0.w, t.x, a00); a01 = fmaf(v0.w, t.y, a01);
                a10 = fmaf(v1.w, t.x, a10); a11 = fmaf(v1.w, t.y, a11);
            }
            __syncthreads();
            issue_chunk(c + 2);   // 2,3 -> U; then 4,5 -> W0,W1
        }
        // h^2, transposed [k][row] — warp-local columns r0,r1
        sh2t[(2 * lane)     * H2S + r0] = __fmul_rn(a00, a00);
        sh2t[(2 * lane + 1) * H2S + r0] = __fmul_rn(a01, a01);
        sh2t[(2 * lane)     * H2S + r1] = __fmul_rn(a10, a10);
        sh2t[(2 * lane + 1) * H2S + r1] = __fmul_rn(a11, a11);
        __syncwarp();

        // GEMM2: christ[2 rows][4 cols] over k; fused v-update
        #pragma unroll 1
        for (int c = 0; c < 4; ++c) {
            CP_WAIT1();
            __syncthreads();
            const float* sW = stage + (c & 1) * 8192;
            const int col = c * 128 + lane * 4;
            const float4 f0 = *(const float4*)(gf + (size_t)(row0 + r0) * DDIM + col);
            const float4 f1 = *(const float4*)(gf + (size_t)(row0 + r1) * DDIM + col);
            float b00 = 0.f, b01 = 0.f, b02 = 0.f, b03 = 0.f;
            float b10 = 0.f, b11 = 0.f, b12 = 0.f, b13 = 0.f;
            const float* wb = sW + lane * 4;
            const float* hb = sh2t + r0;
            #pragma unroll 8
            for (int k = 0; k < KDIM; ++k) {
                float4 wv = *(const float4*)(wb + k * 128);
                float2 hh = *(const float2*)(hb + k * H2S);
                b00 = fmaf(hh.x, wv.x, b00); b01 = fmaf(hh.x, wv.y, b01);
                b02 = fmaf(hh.x, wv.z, b02); b03 = fmaf(hh.x, wv.w, b03);
                b10 = fmaf(hh.y, wv.x, b10); b11 = fmaf(hh.y, wv.y, b11);
                b12 = fmaf(hh.y, wv.z, b12); b13 = fmaf(hh.y, wv.w, b13);
            }
            float4 vv0 = *(float4*)(sv + r0 * DDIM + col);
            vv0.x = __fadd_rn(vv0.x, __fmul_rn(ddt, __fadd_rn(-b00, f0.x)));
            vv0.y = __fadd_rn(vv0.y, __fmul_rn(ddt, __fadd_rn(-b01, f0.y)));
            vv0.z = __fadd_rn(vv0.z, __fmul_rn(ddt, __fadd_rn(-b02, f0.z)));
            vv0.w = __fadd_rn(vv0.w, __fmul_rn(ddt, __fadd_rn(-b03, f0.w)));
            *(float4*)(sv + r0 * DDIM + col) = vv0;
            float4 vv1 = *(float4*)(sv + r1 * DDIM + col);
            vv1.x = __fadd_rn(vv1.x, __fmul_rn(ddt, __fadd_rn(-b10, f1.x)));
            vv1.y = __fadd_rn(vv1.y, __fmul_rn(ddt, __fadd_rn(-b11, f1.y)));
            vv1.z = __fadd_rn(vv1.z, __fmul_rn(ddt, __fadd_rn(-b12, f1.z)));
            vv1.w = __fadd_rn(vv1.w, __fmul_rn(ddt, __fadd_rn(-b13, f1.w)));
            *(float4*)(sv + r1 * DDIM + col) = vv1;
            __syncthreads();
            issue_chunk((c + 6) & 7);   // 6,7 -> W2,W3; then 0,1 -> next eval's U
        }
    };

    for (int s = 0; s < steps; ++s) {
        xup(c1dt);
        eval(d1dt);
        xup(c2dt);
        eval(d2dt);
        xup(c2dt);   // C3 == C2
        eval(d1dt);  // D3 == D1
        xup(c1dt);   // C4 == C1
    }

    // Epilogue is tid-linear across the whole tile -> MUST barrier after the
    // warp-private final xup. (This was the round-2 bug.)
    __syncthreads();
    {
        float4* gox4 = (float4*)(gox + (size_t)row0 * DDIM);
        float4* gov4 = (float4*)(gov + (size_t)row0 * DDIM);
        const float4* sx4 = (const float4*)sx;
        const float4* sv4 = (const float4*)sv;
        #pragma unroll
        for (int i = 0; i < 8; ++i) {
            gox4[tid + i * THREADS] = sx4[tid + i * THREADS];
            gov4[tid + i * THREADS] = sv4[tid + i * THREADS];
        }
    }
    CP_WAIT0();   // drain dangling prefetch groups before exit
}

extern "C" void kernel_launch(void* const* d_in, const int* in_sizes, int n_in,
                              void* d_out, int out_size)
{
    const float* x = (const float*)d_in[0];
    const float* v = (const float*)d_in[1];
    const float* f = (const float*)d_in[2];
    const float* U = (const float*)d_in[3];
    const float* W = (const float*)d_in[4];
    const int* steps = (n_in >= 6) ? (const int*)d_in[5] : nullptr;

    const int B  = in_sizes[0] / DDIM;
    const int BD = B * DDIM;
    float* ox = (float*)d_out;
    float* ov = ox + BD;

    const double theta = 1.0 / (2.0 - pow(2.0, 1.0 / 3.0));
    const float c1dt = (float)((theta / 2.0) * 0.01);
    const float c2dt = (float)(((1.0 - theta) / 2.0) * 0.01);
    const float d1dt = (float)(theta * 0.01);
    const float d2dt = (float)((1.0 - 2.0 * theta) * 0.01);

    const int smem_bytes = (2 * CTA_M * DDIM + KDIM * H2S + 2 * 8192) * 4;  // 205,312 B
    cudaFuncSetAttribute(fr_kernel, cudaFuncAttributeMaxDynamicSharedMemorySize, smem_bytes);
    fr_kernel<<<B / CTA_M, THREADS, smem_bytes>>>(x, v, f, U, W, steps, ox, ov,
                                                  c1dt, c2dt, d1dt, d2dt);
}